// round 6
// baseline (speedup 1.0000x reference)
#include <cuda_runtime.h>
#include <cuda_bf16.h>

// ---- constants from the reference ----
#define ELE_FACTOR 332.0637f
#define EWALD_F    1.12837917f
#define EWALD_P    0.3275911f
#define EA0        0.254829592f
#define EA1       -0.284496736f
#define EA2        1.421413741f
#define EA3       -1.453152027f
#define EA4        1.061405429f
#define COUL_BETA  18.7f
#define COUL_R0    2.2f
#define G_EWALD    0.3f
#define R6_SHIFT   8303.765625f   // 4.5^6
#define INV_CUT6   1.0e-6f        // 1/10^6

#define MAX_ATOMS 200000

// scratch: packed per-atom data (charge, c6, r0, pad). 3.2 MB, L2-resident.
__device__ float4 g_atoms[MAX_ATOMS];

__global__ void pack_atoms_kernel(const float* __restrict__ q,
                                  const float* __restrict__ c6,
                                  const float* __restrict__ r0,
                                  int n) {
    int i = blockIdx.x * blockDim.x + threadIdx.x;
    if (i < n) {
        g_atoms[i] = make_float4(q[i], c6[i], r0[i], 0.0f);
    }
}

// Full per-edge physics. Returns ecoul, edisp and the two force scale factors.
__device__ __forceinline__ void edge_compute(
    float dx, float dy, float dz, float4 A, float4 B,
    float& ecoul, float& edisp, float& fc, float& fd)
{
    float r2     = dx * dx + dy * dy + dz * dz;
    float rinv   = rsqrtf(r2);
    float rij    = r2 * rinv;
    float inv_r2 = rinv * rinv;

    // ---------------- Coulomb ----------------
    float prefactor = ELE_FACTOR * A.x * B.x * rinv;

    float x  = (COUL_BETA / COUL_R0) * (rij - COUL_R0);
    float ex = __expf(-fabsf(x));                     // in (0, 1]
    float inv1pex = __fdividef(1.0f, 1.0f + ex);
    float damp = (x >= 0.0f) ? inv1pex : (ex * inv1pex);   // stable sigmoid
    // softplus(x)/beta, stable
    float sp = (fmaxf(x, 0.0f) + __logf(1.0f + ex)) * (1.0f / COUL_BETA);
    float s  = rij * (1.0f / COUL_R0) * __fdividef(1.0f, 1.0f + sp);

    // Ewald short-range erfc correction
    float grij  = G_EWALD * rij;
    float expm2 = __expf(-grij * grij);
    float t     = __fdividef(1.0f, 1.0f + EWALD_P * grij);
    float erfc  = t * (EA0 + t * (EA1 + t * (EA2 + t * (EA3 + t * EA4)))) * expm2;

    ecoul = prefactor * (s + (erfc - 1.0f));
    float fcoul = prefactor * (damp * s * s + erfc + EWALD_F * grij * expm2 - 1.0f);
    fc = fcoul * inv_r2;

    // ---------------- Dispersion (D3-CSO) ----------------
    float c6ij   = sqrtf(A.y * B.y);
    float r0ij   = 0.5f * (A.z + B.z);
    float r6     = r2 * r2 * r2 + R6_SHIFT;
    float inv_r6 = __fdividef(1.0f, r6);
    float e      = __expf(rij - 2.5f * r0ij);
    float inv1pe = __fdividef(1.0f, 1.0f + e);
    float cso    = 0.85f + 0.82f * inv1pe;

    edisp = -c6ij * inv_r6 * cso + c6ij * INV_CUT6;
    float r5    = r2 * r2 * rij;
    float fdisp = -6.0f * c6ij * r5 * inv_r6 * inv_r6 * cso
                  - c6ij * inv_r6 * (0.82f * e * inv1pe * inv1pe);
    fd = fdisp * rinv;
}

// Vectorized kernel: 4 edges per thread, all streaming traffic 128-bit.
__global__ void __launch_bounds__(256)
bamboo_edge_kernel4(const int4*   __restrict__ row4,
                    const int4*   __restrict__ col4,
                    const float4* __restrict__ dij4,
                    float*        __restrict__ out,
                    int E, int nquads) {
    int t = blockIdx.x * blockDim.x + threadIdx.x;
    if (t >= nquads) return;

    int4 r4 = row4[t];
    int4 c4 = col4[t];
    float4 d0 = dij4[3 * t + 0];
    float4 d1 = dij4[3 * t + 1];
    float4 d2 = dij4[3 * t + 2];

    // de-interleave xyz for the 4 edges
    float dx[4] = { d0.x, d0.w, d1.z, d2.y };
    float dy[4] = { d0.y, d1.x, d1.w, d2.z };
    float dz[4] = { d0.z, d1.y, d2.x, d2.w };
    int   ri[4] = { r4.x, r4.y, r4.z, r4.w };
    int   ci[4] = { c4.x, c4.y, c4.z, c4.w };

    // issue all 8 gathers up front for MLP
    float4 A[4], B[4];
    #pragma unroll
    for (int k = 0; k < 4; k++) {
        A[k] = __ldg(&g_atoms[ri[k]]);
        B[k] = __ldg(&g_atoms[ci[k]]);
    }

    float4 ec, ed;
    float cf[12], df[12];
    #pragma unroll
    for (int k = 0; k < 4; k++) {
        float ecoul, edisp, fc, fd;
        edge_compute(dx[k], dy[k], dz[k], A[k], B[k], ecoul, edisp, fc, fd);
        reinterpret_cast<float*>(&ec)[k] = ecoul;
        reinterpret_cast<float*>(&ed)[k] = edisp;
        cf[3 * k + 0] = dx[k] * fc;
        cf[3 * k + 1] = dy[k] * fc;
        cf[3 * k + 2] = dz[k] * fc;
        df[3 * k + 0] = dx[k] * fd;
        df[3 * k + 1] = dy[k] * fd;
        df[3 * k + 2] = dz[k] * fd;
    }

    // layout: [ecoul E | coul_fij 3E | edisp E | disp_fij 3E]
    reinterpret_cast<float4*>(out)[t] = ec;

    float4* cfp = reinterpret_cast<float4*>(out + (size_t)E) + 3 * t;
    cfp[0] = make_float4(cf[0], cf[1], cf[2],  cf[3]);
    cfp[1] = make_float4(cf[4], cf[5], cf[6],  cf[7]);
    cfp[2] = make_float4(cf[8], cf[9], cf[10], cf[11]);

    reinterpret_cast<float4*>(out + (size_t)4 * E)[t] = ed;

    float4* dfp = reinterpret_cast<float4*>(out + (size_t)5 * E) + 3 * t;
    dfp[0] = make_float4(df[0], df[1], df[2],  df[3]);
    dfp[1] = make_float4(df[4], df[5], df[6],  df[7]);
    dfp[2] = make_float4(df[8], df[9], df[10], df[11]);
}

// scalar tail for E not divisible by 4
__global__ void bamboo_edge_tail(const int*   __restrict__ row,
                                 const int*   __restrict__ col,
                                 const float* __restrict__ dij,
                                 float*       __restrict__ out,
                                 int E, int start) {
    int i = start + blockIdx.x * blockDim.x + threadIdx.x;
    if (i >= E) return;
    float dx = dij[3 * i + 0], dy = dij[3 * i + 1], dz = dij[3 * i + 2];
    float4 A = __ldg(&g_atoms[row[i]]);
    float4 B = __ldg(&g_atoms[col[i]]);
    float ecoul, edisp, fc, fd;
    edge_compute(dx, dy, dz, A, B, ecoul, edisp, fc, fd);
    out[i] = ecoul;
    float* cf = out + (size_t)E + 3 * i;
    cf[0] = dx * fc; cf[1] = dy * fc; cf[2] = dz * fc;
    out[(size_t)4 * E + i] = edisp;
    float* df = out + (size_t)5 * E + 3 * i;
    df[0] = dx * fd; df[1] = dy * fd; df[2] = dz * fd;
}

extern "C" void kernel_launch(void* const* d_in, const int* in_sizes, int n_in,
                              void* d_out, int out_size) {
    const int*   row    = (const int*)d_in[0];
    const int*   col    = (const int*)d_in[1];
    const float* dij    = (const float*)d_in[2];
    const float* charge = (const float*)d_in[3];
    const float* c6     = (const float*)d_in[4];
    const float* r0     = (const float*)d_in[5];
    float* out = (float*)d_out;

    int E = in_sizes[0];
    int N = in_sizes[3];

    const int tpb = 256;
    pack_atoms_kernel<<<(N + tpb - 1) / tpb, tpb>>>(charge, c6, r0, N);

    int nquads = E >> 2;
    if (nquads > 0) {
        bamboo_edge_kernel4<<<(nquads + tpb - 1) / tpb, tpb>>>(
            (const int4*)row, (const int4*)col, (const float4*)dij, out, E, nquads);
    }
    int rem = E - (nquads << 2);
    if (rem > 0) {
        bamboo_edge_tail<<<1, tpb>>>(row, col, dij, out, E, nquads << 2);
    }
}